// round 4
// baseline (speedup 1.0000x reference)
#include <cuda_runtime.h>
#include <math.h>

#define NBLK 128
#define TPB  256
typedef unsigned long long ull;

// ---------------- device scratch ----------------
__device__ float g_h1[2][256 * 256];   // [u][b]
__device__ float g_h2[2][256 * 256];   // [u][b]
__device__ float g_last[256 * 256];    // [b][u]
__device__ float g_y[256 * 256];       // [b][j]
__device__ float g_emb[256 * 256 * 8]; // [t][b][e]
__device__ unsigned g_bar;

struct SmemLayout {
    float Wh0[256 * 32];   // [k][c], c = unit*4 + gate
    float Wi1[256 * 32];
    float Wh1[256 * 32];
    float Wi0[8 * 32];
    float b0[32];
    float b1[32];
    float hsA[256 * 64];   // staged h [k][b_local]
    float hsB[256 * 64];
};

// ---------------- packed f32x2 helpers ----------------
__device__ __forceinline__ ull pk(float a, float b) {
    ull r; asm("mov.b64 %0, {%1,%2};" : "=l"(r) : "f"(a), "f"(b)); return r;
}
__device__ __forceinline__ void unpk(ull v, float& a, float& b) {
    asm("mov.b64 {%0,%1}, %2;" : "=f"(a), "=f"(b) : "l"(v));
}
__device__ __forceinline__ void fma2(ull& acc, ull a, ull b) {
    asm("fma.rn.f32x2 %0, %1, %2, %0;" : "+l"(acc) : "l"(a), "l"(b));
}
__device__ __forceinline__ void add2(ull& acc, ull b) {
    asm("add.rn.f32x2 %0, %0, %1;" : "+l"(acc) : "l"(b));
}

__device__ __forceinline__ float sigf(float x) { return 1.f / (1.f + __expf(-x)); }
__device__ __forceinline__ float tanha(float x) { return 2.f * sigf(2.f * x) - 1.f; }

// ---------------- grid barrier ----------------
__device__ __forceinline__ void grid_sync(unsigned& gen) {
    __syncthreads();
    if (threadIdx.x == 0) {
        __threadfence();
        atomicAdd(&g_bar, 1u);
        gen += NBLK;
        unsigned v;
        do {
            asm volatile("ld.acquire.gpu.global.u32 %0, [%1];" : "=r"(v) : "l"(&g_bar));
        } while (v < gen);
    }
    __syncthreads();
}

// ---------------- cp.async helpers ----------------
__device__ __forceinline__ void cpa16(float* dst_smem, const float* src) {
    unsigned d = (unsigned)__cvta_generic_to_shared(dst_smem);
    asm volatile("cp.async.cg.shared.global [%0], [%1], 16;" :: "r"(d), "l"(src));
}
__device__ __forceinline__ void cpa_commit() { asm volatile("cp.async.commit_group;"); }
#define CPA_WAIT(N) asm volatile("cp.async.wait_group %0;" :: "n"(N))

// stage: global [u][b] slice (cols bg*64.., all 256 u) -> smem [k][64], 256 threads
__device__ __forceinline__ void stage_cg(float* __restrict__ hs,
                                         const float* __restrict__ src,
                                         int bg, int tid) {
    const float* base = src + bg * 64;
#pragma unroll
    for (int i = 0; i < 16; i++) {
        int idx = i * 256 + tid;        // 4096 float4 total
        int k = idx >> 4;
        int seg = (idx & 15) * 4;
        cpa16(hs + k * 64 + seg, base + k * 256 + seg);
    }
}

// ---------------- half-K tile GEMM: thread = 4 rows x 1 unit over 128 k ----------------
__device__ __forceinline__ void gemm8h(const float* __restrict__ sW,
                                       const float* __restrict__ hs,
                                       int txc, int txb, int koff, ull acc[8]) {
    const float4* wp = (const float4*)(sW + koff * 32 + 4 * txc);  // stride 8 f4/k
    const float4* hp = (const float4*)(hs + koff * 64 + 4 * txb);  // stride 16 f4/k
#pragma unroll 8
    for (int k = 0; k < 128; k++) {
        float4 w = wp[k * 8];
        float4 h = hp[k * 16];
        ull w01 = pk(w.x, w.y), w23 = pk(w.z, w.w);
        ull d0 = pk(h.x, h.x), d1 = pk(h.y, h.y);
        ull d2 = pk(h.z, h.z), d3 = pk(h.w, h.w);
        fma2(acc[0], w01, d0); fma2(acc[1], w23, d0);
        fma2(acc[2], w01, d1); fma2(acc[3], w23, d1);
        fma2(acc[4], w01, d2); fma2(acc[5], w23, d2);
        fma2(acc[6], w01, d3); fma2(acc[7], w23, d3);
    }
}

// ---------------- split-K reduction: kh=1 partials -> kh=0 acc ----------------
// red layout [i][w] (ull): bank-friendly. Leading bar orders all gemm reads
// of the buffer being reused before the stores.
__device__ __forceinline__ void reduceK(float* redf, ull acc[8], int kh, int w) {
    ull* red = (ull*)redf;
    __syncthreads();
    if (kh) {
#pragma unroll
        for (int i = 0; i < 8; i++) red[i * 128 + w] = acc[i];
    }
    __syncthreads();
    if (!kh) {
#pragma unroll
        for (int i = 0; i < 8; i++) add2(acc[i], red[i * 128 + w]);
    }
}

__device__ __forceinline__ float lstm_h(ull g01, ull g23, float& cs) {
    float iv, fv, gv, ov;
    unpk(g01, iv, fv); unpk(g23, gv, ov);
    cs = sigf(fv) * cs + sigf(iv) * tanha(gv);
    return sigf(ov) * tanha(cs);
}

// ---------------- prep: embedding gather + barrier reset ----------------
__global__ void prep_kernel(const int* __restrict__ tokens,
                            const float* __restrict__ emb) {
    int idx = blockIdx.x * 256 + threadIdx.x;  // 0..65535
    if (idx == 0) g_bar = 0;
    int b = idx >> 8, t = idx & 255;
    int tok = tokens[b * 256 + t];
    const float4* e = (const float4*)(emb + tok * 8);
    float4* d = (float4*)(g_emb + (t * 256 + b) * 8);
    d[0] = e[0];
    d[1] = e[1];
}

// ---------------- persistent LSTM kernel ----------------
extern __shared__ float smem_raw[];

__global__ void __launch_bounds__(TPB, 1)
lstm_kernel(const int* __restrict__ lengths,
            const float* __restrict__ w_ih0, const float* __restrict__ w_hh0,
            const float* __restrict__ b_ih0, const float* __restrict__ b_hh0,
            const float* __restrict__ w_ih1, const float* __restrict__ w_hh1,
            const float* __restrict__ b_ih1, const float* __restrict__ b_hh1,
            const float* __restrict__ ff_w, const float* __restrict__ ff_b,
            const float* __restrict__ bn_g, const float* __restrict__ bn_b,
            float* __restrict__ out) {
    SmemLayout* S = (SmemLayout*)smem_raw;
    const int tid = threadIdx.x;
    const int bid = blockIdx.x;
    const int bg = bid >> 5;     // batch group 0..3 (64 rows)
    const int ug = bid & 31;     // unit group 0..31 (8 units)
    const int kh = tid >> 7;     // k-half: 0 -> k[0,128), 1 -> k[128,256)
    const int w  = tid & 127;    // lane within team
    const int txc = w & 7;       // unit within group
    const int txb = w >> 3;      // 0..15 -> rows 4*txb..4*txb+3
    const int koff = kh * 128;
    const int rb = bg * 64 + 4 * txb;
    const int u = ug * 8 + txc;

    // --- load + permute weights into SMEM ---
    for (int idx = tid; idx < 32 * 256; idx += TPB) {
        int c = idx & 31, k = idx >> 5;
        int uu = c >> 2, g = c & 3;
        int row = g * 256 + ug * 8 + uu;
        S->Wh0[k * 32 + c] = w_hh0[row * 256 + k];
        S->Wi1[k * 32 + c] = w_ih1[row * 256 + k];
        S->Wh1[k * 32 + c] = w_hh1[row * 256 + k];
    }
    if (tid < 8 * 32) {
        int c = tid & 31, e = tid >> 5;
        int uu = c >> 2, g = c & 3;
        int row = g * 256 + ug * 8 + uu;
        S->Wi0[e * 32 + c] = w_ih0[row * 8 + e];
    }
    if (tid < 32) {
        int uu = tid >> 2, g = tid & 3;
        int row = g * 256 + ug * 8 + uu;
        S->b0[tid] = b_ih0[row] + b_hh0[row];
        S->b1[tid] = b_ih1[row] + b_hh1[row];
    }
    // zero initial state buffers (parity 1 is read at t=0); kh teams write same zeros
    if (!kh) {
        float4 z4 = make_float4(0.f, 0.f, 0.f, 0.f);
        *(float4*)(&g_h1[1][u * 256 + rb]) = z4;
        *(float4*)(&g_h2[1][u * 256 + rb]) = z4;
    }

    int4 ln4 = *(const int4*)(lengths + rb);
    int ln[4] = {ln4.x, ln4.y, ln4.z, ln4.w};
    float c1s[4] = {0.f, 0.f, 0.f, 0.f};
    float c2s[4] = {0.f, 0.f, 0.f, 0.f};
    unsigned gen = 0;
    grid_sync(gen);

    // prefetch initial h1 (zeros) into P
    float* P = S->hsA;
    float* Q = S->hsB;
    stage_cg(P, g_h1[1], bg, tid);
    cpa_commit();

    ull bi01_0 = pk(S->b0[4 * txc + 0], S->b0[4 * txc + 1]);
    ull bi23_0 = pk(S->b0[4 * txc + 2], S->b0[4 * txc + 3]);
    ull bi01_1 = pk(S->b1[4 * txc + 0], S->b1[4 * txc + 1]);
    ull bi23_1 = pk(S->b1[4 * txc + 2], S->b1[4 * txc + 3]);
    const ull Z = 0ull;

    for (int t = 0; t < 256; t++) {
        const int wpar = t & 1;
        const int rpar = wpar ^ 1;

        CPA_WAIT(0);
        __syncthreads();                 // P holds h1(t-1)

        // ================= layer 0 =================
        ull a[8];
        if (!kh) {
            a[0] = a[2] = a[4] = a[6] = bi01_0;
            a[1] = a[3] = a[5] = a[7] = bi23_0;
            // x-part (only once, by team 0)
            const float4* ep = (const float4*)(g_emb + (t * 256 + rb) * 8);
            float xv[4][8];
#pragma unroll
            for (int r = 0; r < 4; r++) {
                float4 u0 = ep[2 * r], u1 = ep[2 * r + 1];
                xv[r][0] = u0.x; xv[r][1] = u0.y; xv[r][2] = u0.z; xv[r][3] = u0.w;
                xv[r][4] = u1.x; xv[r][5] = u1.y; xv[r][6] = u1.z; xv[r][7] = u1.w;
            }
#pragma unroll
            for (int e = 0; e < 8; e++) {
                float4 wv = *(const float4*)(&S->Wi0[e * 32 + 4 * txc]);
                ull w01 = pk(wv.x, wv.y), w23 = pk(wv.z, wv.w);
#pragma unroll
                for (int r = 0; r < 4; r++) {
                    ull xd = pk(xv[r][e], xv[r][e]);
                    fma2(a[2 * r], w01, xd);
                    fma2(a[2 * r + 1], w23, xd);
                }
            }
        } else {
#pragma unroll
            for (int i = 0; i < 8; i++) a[i] = Z;
        }
        gemm8h(S->Wh0, P, txc, txb, koff, a);
        reduceK(Q, a, kh, w);            // Q is dead here; bars inside

        float h1v[4];
        if (!kh) {
#pragma unroll
            for (int r = 0; r < 4; r++)
                h1v[r] = lstm_h(a[2 * r], a[2 * r + 1], c1s[r]);
            *(float4*)(&g_h1[wpar][u * 256 + rb]) =
                make_float4(h1v[0], h1v[1], h1v[2], h1v[3]);
        }

        grid_sync(gen);                  // the ONLY grid barrier per step

        // ================= layer 1 =================
        stage_cg(Q, g_h1[wpar], bg, tid);   // h1(t)    group 0
        cpa_commit();
        stage_cg(P, g_h2[rpar], bg, tid);   // h2(t-1)  group 1
        cpa_commit();

        if (!kh) {
            a[0] = a[2] = a[4] = a[6] = bi01_1;
            a[1] = a[3] = a[5] = a[7] = bi23_1;
        } else {
#pragma unroll
            for (int i = 0; i < 8; i++) a[i] = Z;
        }

        CPA_WAIT(1);
        __syncthreads();                    // Q ready
        gemm8h(S->Wi1, Q, txc, txb, koff, a);

        CPA_WAIT(0);
        __syncthreads();                    // P ready
        gemm8h(S->Wh1, P, txc, txb, koff, a);
        reduceK(P, a, kh, w);               // P (h2(t-1)) dead; bars inside

        if (!kh) {
            float h2v[4];
#pragma unroll
            for (int r = 0; r < 4; r++)
                h2v[r] = lstm_h(a[2 * r], a[2 * r + 1], c2s[r]);
            *(float4*)(&g_h2[wpar][u * 256 + rb]) =
                make_float4(h2v[0], h2v[1], h2v[2], h2v[3]);
#pragma unroll
            for (int r = 0; r < 4; r++)
                if (t == ln[r] - 1) g_last[(rb + r) * 256 + u] = h2v[r];
        }

        float* tmp = P; P = Q; Q = tmp;     // Q holds h1(t) = next L0 input
    }

    grid_sync(gen);

    // ================= y = relu(last) @ ff_w^T + ff_b =================
    // block handles batch rows 2*bid, 2*bid+1; thread = col tid (256 cols)
    {
        float* sv = S->hsA;
        int br0 = 2 * bid, br1 = 2 * bid + 1;
        sv[tid]       = fmaxf(g_last[br0 * 256 + tid], 0.f);
        sv[256 + tid] = fmaxf(g_last[br1 * 256 + tid], 0.f);
        __syncthreads();
        float a0 = ff_b[tid], a1 = a0;
        const float4* wr = (const float4*)(ff_w + tid * 256);
        const float4* h0 = (const float4*)sv;
        const float4* h1 = (const float4*)(sv + 256);
#pragma unroll 4
        for (int k4 = 0; k4 < 64; k4++) {
            float4 wv = wr[k4];
            float4 ha = h0[k4], hb = h1[k4];
            a0 += wv.x * ha.x + wv.y * ha.y + wv.z * ha.z + wv.w * ha.w;
            a1 += wv.x * hb.x + wv.y * hb.y + wv.z * hb.z + wv.w * hb.w;
        }
        g_y[br0 * 256 + tid] = a0;
        g_y[br1 * 256 + tid] = a1;
    }

    grid_sync(gen);

    // ================= BatchNorm over batch axis =================
    // block handles cols 2*bid, 2*bid+1; thread = batch row tid (256 rows)
    {
        float* red = S->hsA;
        for (int r = 0; r < 2; r++) {
            int j = 2 * bid + r;
            float v = g_y[tid * 256 + j];
            __syncthreads();
            red[tid] = v;
            __syncthreads();
            for (int s = 128; s > 0; s >>= 1) {
                if (tid < s) red[tid] += red[tid + s];
                __syncthreads();
            }
            float mean = red[0] * (1.f / 256.f);
            __syncthreads();
            float d = v - mean;
            red[tid] = d * d;
            __syncthreads();
            for (int s = 128; s > 0; s >>= 1) {
                if (tid < s) red[tid] += red[tid + s];
                __syncthreads();
            }
            float inv = rsqrtf(red[0] * (1.f / 256.f) + 1e-5f);
            __syncthreads();
            out[tid * 256 + j] = bn_g[j] * d * inv + bn_b[j];
        }
    }
}

// ---------------- launch ----------------
extern "C" void kernel_launch(void* const* d_in, const int* in_sizes, int n_in,
                              void* d_out, int out_size) {
    const int*   tokens    = (const int*)d_in[0];
    const int*   lengths   = (const int*)d_in[1];
    const float* embedding = (const float*)d_in[2];
    const float* w_ih0     = (const float*)d_in[3];
    const float* w_hh0     = (const float*)d_in[4];
    const float* b_ih0     = (const float*)d_in[5];
    const float* b_hh0     = (const float*)d_in[6];
    const float* w_ih1     = (const float*)d_in[7];
    const float* w_hh1     = (const float*)d_in[8];
    const float* b_ih1     = (const float*)d_in[9];
    const float* b_hh1     = (const float*)d_in[10];
    const float* ff_w      = (const float*)d_in[11];
    const float* ff_b      = (const float*)d_in[12];
    const float* bn_g      = (const float*)d_in[13];
    const float* bn_b      = (const float*)d_in[14];
    float* out = (float*)d_out;

    cudaFuncSetAttribute(lstm_kernel, cudaFuncAttributeMaxDynamicSharedMemorySize,
                         (int)sizeof(SmemLayout));

    prep_kernel<<<256, 256>>>(tokens, embedding);
    lstm_kernel<<<NBLK, TPB, sizeof(SmemLayout)>>>(
        lengths, w_ih0, w_hh0, b_ih0, b_hh0,
        w_ih1, w_hh1, b_ih1, b_hh1,
        ff_w, ff_b, bn_g, bn_b, out);
}

// round 5
// speedup vs baseline: 1.0846x; 1.0846x over previous
#include <cuda_runtime.h>
#include <math.h>

#define NBLK 128
#define TPB  256
typedef unsigned long long ull;

// ---------------- device scratch ----------------
__device__ float g_h1[2][256 * 256];   // [u][b]
__device__ float g_h2[2][256 * 256];   // [u][b]
__device__ float g_last[256 * 256];    // [b][u]
__device__ float g_y[256 * 256];       // [b][j]
__device__ float g_emb[256 * 256 * 8]; // [t][b][e]
__device__ unsigned g_bar;

struct SmemLayout {
    float Wh0[256 * 32];   // [k][c], c = unit*4 + gate
    float Wi1[256 * 32];
    float Wh1[256 * 32];
    float Wi0[8 * 32];
    float b0[32];
    float b1[32];
    float hsA[256 * 64];   // staged h1 tile [k][b_local]; also reduce scratch A
    float hsB[256 * 64];   // staged h2 tile; also reduce scratch B
};

// ---------------- packed f32x2 helpers ----------------
__device__ __forceinline__ ull pk(float a, float b) {
    ull r; asm("mov.b64 %0, {%1,%2};" : "=l"(r) : "f"(a), "f"(b)); return r;
}
__device__ __forceinline__ void unpk(ull v, float& a, float& b) {
    asm("mov.b64 {%0,%1}, %2;" : "=f"(a), "=f"(b) : "l"(v));
}
__device__ __forceinline__ void fma2(ull& acc, ull a, ull b) {
    asm("fma.rn.f32x2 %0, %1, %2, %0;" : "+l"(acc) : "l"(a), "l"(b));
}
__device__ __forceinline__ void add2(ull& acc, ull b) {
    asm("add.rn.f32x2 %0, %0, %1;" : "+l"(acc) : "l"(b));
}

__device__ __forceinline__ float sigf(float x) { return 1.f / (1.f + __expf(-x)); }
__device__ __forceinline__ float tanha(float x) { return 2.f * sigf(2.f * x) - 1.f; }

// ---------------- grid barrier ----------------
__device__ __forceinline__ void grid_sync(unsigned& gen) {
    __syncthreads();
    if (threadIdx.x == 0) {
        __threadfence();
        atomicAdd(&g_bar, 1u);
        gen += NBLK;
        unsigned v;
        do {
            asm volatile("ld.acquire.gpu.global.u32 %0, [%1];" : "=r"(v) : "l"(&g_bar));
        } while (v < gen);
    }
    __syncthreads();
}

// ---------------- cp.async helpers ----------------
__device__ __forceinline__ void cpa16(float* dst_smem, const float* src) {
    unsigned d = (unsigned)__cvta_generic_to_shared(dst_smem);
    asm volatile("cp.async.cg.shared.global [%0], [%1], 16;" :: "r"(d), "l"(src));
}
__device__ __forceinline__ void cpa_commit() { asm volatile("cp.async.commit_group;"); }
#define CPA_WAIT(N) asm volatile("cp.async.wait_group %0;" :: "n"(N))

// stage: global [u][b] slice (cols bg*64.., all 256 u) -> smem [k][64], 256 threads
__device__ __forceinline__ void stage_cg(float* __restrict__ hs,
                                         const float* __restrict__ src,
                                         int bg, int tid) {
    const float* base = src + bg * 64;
#pragma unroll
    for (int i = 0; i < 16; i++) {
        int idx = i * 256 + tid;        // 4096 float4 total
        int k = idx >> 4;
        int seg = (idx & 15) * 4;
        cpa16(hs + k * 64 + seg, base + k * 256 + seg);
    }
}

// ---------------- half-K tile GEMM: thread = 4 rows x 1 unit over 128 k ----------------
__device__ __forceinline__ void gemm8h(const float* __restrict__ sW,
                                       const float* __restrict__ hs,
                                       int txc, int txb, int koff, ull acc[8]) {
    const float4* wp = (const float4*)(sW + koff * 32 + 4 * txc);  // stride 8 f4/k
    const float4* hp = (const float4*)(hs + koff * 64 + 4 * txb);  // stride 16 f4/k
#pragma unroll 8
    for (int k = 0; k < 128; k++) {
        float4 w = wp[k * 8];
        float4 h = hp[k * 16];
        ull w01 = pk(w.x, w.y), w23 = pk(w.z, w.w);
        ull d0 = pk(h.x, h.x), d1 = pk(h.y, h.y);
        ull d2 = pk(h.z, h.z), d3 = pk(h.w, h.w);
        fma2(acc[0], w01, d0); fma2(acc[1], w23, d0);
        fma2(acc[2], w01, d1); fma2(acc[3], w23, d1);
        fma2(acc[4], w01, d2); fma2(acc[5], w23, d2);
        fma2(acc[6], w01, d3); fma2(acc[7], w23, d3);
    }
}

// ---------------- combined split-K reduction ----------------
// a0 final lands in kh=0 (L0 team), a1 final lands in kh=1 (L1 team).
// Uses hsA/hsB (dead after gemms) as scratch; leading bar orders gemm reads.
__device__ __forceinline__ void reduce_both(float* bufA, float* bufB,
                                            ull a0[8], ull a1[8], int kh, int w) {
    ull* rA = (ull*)bufA;
    ull* rB = (ull*)bufB;
    __syncthreads();
    if (kh) {
#pragma unroll
        for (int i = 0; i < 8; i++) rA[i * 128 + w] = a0[i];
    } else {
#pragma unroll
        for (int i = 0; i < 8; i++) rB[i * 128 + w] = a1[i];
    }
    __syncthreads();
    if (!kh) {
#pragma unroll
        for (int i = 0; i < 8; i++) add2(a0[i], rA[i * 128 + w]);
    } else {
#pragma unroll
        for (int i = 0; i < 8; i++) add2(a1[i], rB[i * 128 + w]);
    }
}

__device__ __forceinline__ float lstm_h(ull g01, ull g23, float& cs) {
    float iv, fv, gv, ov;
    unpk(g01, iv, fv); unpk(g23, gv, ov);
    cs = sigf(fv) * cs + sigf(iv) * tanha(gv);
    return sigf(ov) * tanha(cs);
}

// x-part of L0 gates for timestep t (4 batch rows rb..rb+3, unit txc)
__device__ __forceinline__ void xpart(const float* __restrict__ Wi0,
                                      int t, int rb, int txc, ull a[8]) {
    const float4* ep = (const float4*)(g_emb + (t * 256 + rb) * 8);
    float xv[4][8];
#pragma unroll
    for (int r = 0; r < 4; r++) {
        float4 u0 = ep[2 * r], u1 = ep[2 * r + 1];
        xv[r][0] = u0.x; xv[r][1] = u0.y; xv[r][2] = u0.z; xv[r][3] = u0.w;
        xv[r][4] = u1.x; xv[r][5] = u1.y; xv[r][6] = u1.z; xv[r][7] = u1.w;
    }
#pragma unroll
    for (int e = 0; e < 8; e++) {
        float4 wv = *(const float4*)(&Wi0[e * 32 + 4 * txc]);
        ull w01 = pk(wv.x, wv.y), w23 = pk(wv.z, wv.w);
#pragma unroll
        for (int r = 0; r < 4; r++) {
            ull xd = pk(xv[r][e], xv[r][e]);
            fma2(a[2 * r], w01, xd);
            fma2(a[2 * r + 1], w23, xd);
        }
    }
}

// ---------------- prep: embedding gather + barrier reset ----------------
__global__ void prep_kernel(const int* __restrict__ tokens,
                            const float* __restrict__ emb) {
    int idx = blockIdx.x * 256 + threadIdx.x;  // 0..65535
    if (idx == 0) g_bar = 0;
    int b = idx >> 8, t = idx & 255;
    int tok = tokens[b * 256 + t];
    const float4* e = (const float4*)(emb + tok * 8);
    float4* d = (float4*)(g_emb + (t * 256 + b) * 8);
    d[0] = e[0];
    d[1] = e[1];
}

// ---------------- persistent LSTM kernel ----------------
extern __shared__ float smem_raw[];

__global__ void __launch_bounds__(TPB, 1)
lstm_kernel(const int* __restrict__ lengths,
            const float* __restrict__ w_ih0, const float* __restrict__ w_hh0,
            const float* __restrict__ b_ih0, const float* __restrict__ b_hh0,
            const float* __restrict__ w_ih1, const float* __restrict__ w_hh1,
            const float* __restrict__ b_ih1, const float* __restrict__ b_hh1,
            const float* __restrict__ ff_w, const float* __restrict__ ff_b,
            const float* __restrict__ bn_g, const float* __restrict__ bn_b,
            float* __restrict__ out) {
    SmemLayout* S = (SmemLayout*)smem_raw;
    const int tid = threadIdx.x;
    const int bid = blockIdx.x;
    const int bg = bid >> 5;     // batch group 0..3 (64 rows)
    const int ug = bid & 31;     // unit group 0..31 (8 units)
    const int kh = tid >> 7;     // k-half team: 0 -> k[0,128) + L0 cell; 1 -> k[128,256) + L1 cell
    const int w  = tid & 127;
    const int txc = w & 7;       // unit within group
    const int txb = w >> 3;      // 0..15 -> rows 4*txb..4*txb+3
    const int koff = kh * 128;
    const int rb = bg * 64 + 4 * txb;
    const int u = ug * 8 + txc;

    // --- load + permute weights into SMEM ---
    for (int idx = tid; idx < 32 * 256; idx += TPB) {
        int c = idx & 31, k = idx >> 5;
        int uu = c >> 2, g = c & 3;
        int row = g * 256 + ug * 8 + uu;
        S->Wh0[k * 32 + c] = w_hh0[row * 256 + k];
        S->Wi1[k * 32 + c] = w_ih1[row * 256 + k];
        S->Wh1[k * 32 + c] = w_hh1[row * 256 + k];
    }
    if (tid < 8 * 32) {
        int c = tid & 31, e = tid >> 5;
        int uu = c >> 2, g = c & 3;
        int row = g * 256 + ug * 8 + uu;
        S->Wi0[e * 32 + c] = w_ih0[row * 8 + e];
    }
    if (tid < 32) {
        int uu = tid >> 2, g = tid & 3;
        int row = g * 256 + ug * 8 + uu;
        S->b0[tid] = b_ih0[row] + b_hh0[row];
        S->b1[tid] = b_ih1[row] + b_hh1[row];
    }
    // h2(-1) = 0 lives in g_h2[1] (read at phase 0)
    if (!kh) {
        *(float4*)(&g_h2[1][u * 256 + rb]) = make_float4(0.f, 0.f, 0.f, 0.f);
    }

    int4 ln4 = *(const int4*)(lengths + rb);
    int ln[4] = {ln4.x, ln4.y, ln4.z, ln4.w};
    float c1s[4] = {0.f, 0.f, 0.f, 0.f};
    float c2s[4] = {0.f, 0.f, 0.f, 0.f};
    unsigned gen = 0;
    __syncthreads();   // smem biases ready for prologue

    ull bi01_0 = pk(S->b0[4 * txc + 0], S->b0[4 * txc + 1]);
    ull bi23_0 = pk(S->b0[4 * txc + 2], S->b0[4 * txc + 3]);
    ull bi01_1 = pk(S->b1[4 * txc + 0], S->b1[4 * txc + 1]);
    ull bi23_1 = pk(S->b1[4 * txc + 2], S->b1[4 * txc + 3]);
    const ull Z = 0ull;

    // ---------- prologue: h1(0) = cell(x(0), 0)  (no cross-block sum needed) ----------
    if (!kh) {
        ull a0[8];
        a0[0] = a0[2] = a0[4] = a0[6] = bi01_0;
        a0[1] = a0[3] = a0[5] = a0[7] = bi23_0;
        xpart(S->Wi0, 0, rb, txc, a0);
        float h1v[4];
#pragma unroll
        for (int r = 0; r < 4; r++)
            h1v[r] = lstm_h(a0[2 * r], a0[2 * r + 1], c1s[r]);
        *(float4*)(&g_h1[0][u * 256 + rb]) =
            make_float4(h1v[0], h1v[1], h1v[2], h1v[3]);
    }
    grid_sync(gen);

    // ---------- main loop: phase p computes h1(p+1) and h2(p) ----------
    for (int p = 0; p < 255; p++) {
        const int cb = p & 1;   // h1(p) in g_h1[cb], h2(p-1) in g_h2[cb^1]

        stage_cg(S->hsA, g_h1[cb], bg, tid);      // h1(p)    group 0
        cpa_commit();
        stage_cg(S->hsB, g_h2[cb ^ 1], bg, tid);  // h2(p-1)  group 1
        cpa_commit();

        ull a0[8], a1[8];
        if (!kh) {
            a0[0] = a0[2] = a0[4] = a0[6] = bi01_0;
            a0[1] = a0[3] = a0[5] = a0[7] = bi23_0;
            xpart(S->Wi0, p + 1, rb, txc, a0);    // x(p+1), overlaps stage latency
#pragma unroll
            for (int i = 0; i < 8; i++) a1[i] = Z;
        } else {
#pragma unroll
            for (int i = 0; i < 8; i++) a0[i] = Z;
            a1[0] = a1[2] = a1[4] = a1[6] = bi01_1;
            a1[1] = a1[3] = a1[5] = a1[7] = bi23_1;
        }

        CPA_WAIT(1);
        __syncthreads();                          // hsA (h1(p)) ready
        gemm8h(S->Wh0, S->hsA, txc, txb, koff, a0);
        gemm8h(S->Wi1, S->hsA, txc, txb, koff, a1);

        CPA_WAIT(0);
        __syncthreads();                          // hsB (h2(p-1)) ready
        gemm8h(S->Wh1, S->hsB, txc, txb, koff, a1);

        reduce_both(S->hsA, S->hsB, a0, a1, kh, w);

        if (!kh) {
            float h1v[4];
#pragma unroll
            for (int r = 0; r < 4; r++)
                h1v[r] = lstm_h(a0[2 * r], a0[2 * r + 1], c1s[r]);
            *(float4*)(&g_h1[cb ^ 1][u * 256 + rb]) =
                make_float4(h1v[0], h1v[1], h1v[2], h1v[3]);   // h1(p+1)
        } else {
            float h2v[4];
#pragma unroll
            for (int r = 0; r < 4; r++)
                h2v[r] = lstm_h(a1[2 * r], a1[2 * r + 1], c2s[r]);
            *(float4*)(&g_h2[cb][u * 256 + rb]) =
                make_float4(h2v[0], h2v[1], h2v[2], h2v[3]);   // h2(p)
#pragma unroll
            for (int r = 0; r < 4; r++)
                if (p == ln[r] - 1) g_last[(rb + r) * 256 + u] = h2v[r];
        }

        grid_sync(gen);
    }

    // ---------- epilogue: h2(255) from h1(255) (buf 1) and h2(254) (buf 0) ----------
    {
        stage_cg(S->hsA, g_h1[1], bg, tid);
        cpa_commit();
        stage_cg(S->hsB, g_h2[0], bg, tid);
        cpa_commit();

        ull a1[8];
        if (kh) {
            a1[0] = a1[2] = a1[4] = a1[6] = bi01_1;
            a1[1] = a1[3] = a1[5] = a1[7] = bi23_1;
        } else {
#pragma unroll
            for (int i = 0; i < 8; i++) a1[i] = Z;
        }

        CPA_WAIT(1);
        __syncthreads();
        gemm8h(S->Wi1, S->hsA, txc, txb, koff, a1);
        CPA_WAIT(0);
        __syncthreads();
        gemm8h(S->Wh1, S->hsB, txc, txb, koff, a1);

        ull* rB = (ull*)S->hsB;
        __syncthreads();
        if (!kh) {
#pragma unroll
            for (int i = 0; i < 8; i++) rB[i * 128 + w] = a1[i];
        }
        __syncthreads();
        if (kh) {
#pragma unroll
            for (int i = 0; i < 8; i++) add2(a1[i], rB[i * 128 + w]);
            float h2v[4];
#pragma unroll
            for (int r = 0; r < 4; r++)
                h2v[r] = lstm_h(a1[2 * r], a1[2 * r + 1], c2s[r]);
#pragma unroll
            for (int r = 0; r < 4; r++)
                if (ln[r] == 256) g_last[(rb + r) * 256 + u] = h2v[r];
        }
    }

    grid_sync(gen);

    // ================= y = relu(last) @ ff_w^T + ff_b =================
    // block handles batch rows 2*bid, 2*bid+1; thread = col tid (256 cols)
    {
        float* sv = S->hsA;
        int br0 = 2 * bid, br1 = 2 * bid + 1;
        sv[tid]       = fmaxf(g_last[br0 * 256 + tid], 0.f);
        sv[256 + tid] = fmaxf(g_last[br1 * 256 + tid], 0.f);
        __syncthreads();
        float a0 = ff_b[tid], a1 = a0;
        const float4* wr = (const float4*)(ff_w + tid * 256);
        const float4* h0 = (const float4*)sv;
        const float4* h1 = (const float4*)(sv + 256);
#pragma unroll 4
        for (int k4 = 0; k4 < 64; k4++) {
            float4 wv = wr[k4];
            float4 ha = h0[k4], hb = h1[k4];
            a0 += wv.x * ha.x + wv.y * ha.y + wv.z * ha.z + wv.w * ha.w;
            a1 += wv.x * hb.x + wv.y * hb.y + wv.z * hb.z + wv.w * hb.w;
        }
        g_y[br0 * 256 + tid] = a0;
        g_y[br1 * 256 + tid] = a1;
    }

    grid_sync(gen);

    // ================= BatchNorm over batch axis =================
    // block handles cols 2*bid, 2*bid+1; thread = batch row tid (256 rows)
    {
        float* red = S->hsA;
        for (int r = 0; r < 2; r++) {
            int j = 2 * bid + r;
            float v = g_y[tid * 256 + j];
            __syncthreads();
            red[tid] = v;
            __syncthreads();
            for (int s = 128; s > 0; s >>= 1) {
                if (tid < s) red[tid] += red[tid + s];
                __syncthreads();
            }
            float mean = red[0] * (1.f / 256.f);
            __syncthreads();
            float d = v - mean;
            red[tid] = d * d;
            __syncthreads();
            for (int s = 128; s > 0; s >>= 1) {
                if (tid < s) red[tid] += red[tid + s];
                __syncthreads();
            }
            float inv = rsqrtf(red[0] * (1.f / 256.f) + 1e-5f);
            __syncthreads();
            out[tid * 256 + j] = bn_g[j] * d * inv + bn_b[j];
        }
    }
}

// ---------------- launch ----------------
extern "C" void kernel_launch(void* const* d_in, const int* in_sizes, int n_in,
                              void* d_out, int out_size) {
    const int*   tokens    = (const int*)d_in[0];
    const int*   lengths   = (const int*)d_in[1];
    const float* embedding = (const float*)d_in[2];
    const float* w_ih0     = (const float*)d_in[3];
    const float* w_hh0     = (const float*)d_in[4];
    const float* b_ih0     = (const float*)d_in[5];
    const float* b_hh0     = (const float*)d_in[6];
    const float* w_ih1     = (const float*)d_in[7];
    const float* w_hh1     = (const float*)d_in[8];
    const float* b_ih1     = (const float*)d_in[9];
    const float* b_hh1     = (const float*)d_in[10];
    const float* ff_w      = (const float*)d_in[11];
    const float* ff_b      = (const float*)d_in[12];
    const float* bn_g      = (const float*)d_in[13];
    const float* bn_b      = (const float*)d_in[14];
    float* out = (float*)d_out;

    cudaFuncSetAttribute(lstm_kernel, cudaFuncAttributeMaxDynamicSharedMemorySize,
                         (int)sizeof(SmemLayout));

    prep_kernel<<<256, 256>>>(tokens, embedding);
    lstm_kernel<<<NBLK, TPB, sizeof(SmemLayout)>>>(
        lengths, w_ih0, w_hh0, b_ih0, b_hh0,
        w_ih1, w_hh1, b_ih1, b_hh1,
        ff_w, ff_b, bn_g, bn_b, out);
}

// round 6
// speedup vs baseline: 1.0852x; 1.0006x over previous
#include <cuda_runtime.h>
#include <math.h>

#define NBLK 128
#define TPB  256
typedef unsigned long long ull;

// ---------------- device scratch ----------------
__device__ float g_h1[2][256 * 256];   // [u][b]
__device__ float g_h2[2][256 * 256];   // [u][b]
__device__ float g_last[256 * 256];    // [b][u]
__device__ float g_y[256 * 256];       // [b][j]
__device__ float g_emb[256 * 256 * 8]; // [t][b][e]
__device__ unsigned g_bar;

struct SmemLayout {
    float Wh0[256 * 32];   // [k][c], c = unit*4 + gate
    float Wi1[256 * 32];
    float Wh1[256 * 32];
    float Wi0[8 * 32];
    float b0[32];
    float b1[32];
    float hsA[256 * 64];   // staged h1 tile [k][b_local]; also reduce scratch A
    float hsB[256 * 64];   // staged h2 tile; also reduce scratch B
};

// ---------------- packed f32x2 helpers ----------------
__device__ __forceinline__ ull pk(float a, float b) {
    ull r; asm("mov.b64 %0, {%1,%2};" : "=l"(r) : "f"(a), "f"(b)); return r;
}
__device__ __forceinline__ void unpk(ull v, float& a, float& b) {
    asm("mov.b64 {%0,%1}, %2;" : "=f"(a), "=f"(b) : "l"(v));
}
__device__ __forceinline__ void fma2(ull& acc, ull a, ull b) {
    asm("fma.rn.f32x2 %0, %1, %2, %0;" : "+l"(acc) : "l"(a), "l"(b));
}
__device__ __forceinline__ void add2(ull& acc, ull b) {
    asm("add.rn.f32x2 %0, %0, %1;" : "+l"(acc) : "l"(b));
}

__device__ __forceinline__ float sigf(float x) { return 1.f / (1.f + __expf(-x)); }
__device__ __forceinline__ float tanha(float x) { return 2.f * sigf(2.f * x) - 1.f; }

// ---------------- grid barrier ----------------
__device__ __forceinline__ void grid_sync(unsigned& gen) {
    __syncthreads();
    if (threadIdx.x == 0) {
        __threadfence();
        atomicAdd(&g_bar, 1u);
        gen += NBLK;
        unsigned v;
        do {
            asm volatile("ld.acquire.gpu.global.u32 %0, [%1];" : "=r"(v) : "l"(&g_bar));
        } while (v < gen);
    }
    __syncthreads();
}

// ---------------- cp.async helpers ----------------
__device__ __forceinline__ void cpa16(float* dst_smem, const float* src) {
    unsigned d = (unsigned)__cvta_generic_to_shared(dst_smem);
    asm volatile("cp.async.cg.shared.global [%0], [%1], 16;" :: "r"(d), "l"(src));
}
__device__ __forceinline__ void cpa_commit() { asm volatile("cp.async.commit_group;"); }
#define CPA_WAIT(N) asm volatile("cp.async.wait_group %0;" :: "n"(N))

// stage: global [u][b] slice (cols bg*64.., all 256 u) -> smem [k][64], 256 threads
__device__ __forceinline__ void stage_cg(float* __restrict__ hs,
                                         const float* __restrict__ src,
                                         int bg, int tid) {
    const float* base = src + bg * 64;
#pragma unroll
    for (int i = 0; i < 16; i++) {
        int idx = i * 256 + tid;        // 4096 float4 total
        int k = idx >> 4;
        int seg = (idx & 15) * 4;
        cpa16(hs + k * 64 + seg, base + k * 256 + seg);
    }
}

// ---------------- half-K tile GEMM: thread = 4 rows x 1 unit over 128 k ----------------
__device__ __forceinline__ void gemm8h(const float* __restrict__ sW,
                                       const float* __restrict__ hs,
                                       int txc, int txb, int koff, ull acc[8]) {
    const float4* wp = (const float4*)(sW + koff * 32 + 4 * txc);  // stride 8 f4/k
    const float4* hp = (const float4*)(hs + koff * 64 + 4 * txb);  // stride 16 f4/k
#pragma unroll 8
    for (int k = 0; k < 128; k++) {
        float4 w = wp[k * 8];
        float4 h = hp[k * 16];
        ull w01 = pk(w.x, w.y), w23 = pk(w.z, w.w);
        ull d0 = pk(h.x, h.x), d1 = pk(h.y, h.y);
        ull d2 = pk(h.z, h.z), d3 = pk(h.w, h.w);
        fma2(acc[0], w01, d0); fma2(acc[1], w23, d0);
        fma2(acc[2], w01, d1); fma2(acc[3], w23, d1);
        fma2(acc[4], w01, d2); fma2(acc[5], w23, d2);
        fma2(acc[6], w01, d3); fma2(acc[7], w23, d3);
    }
}

// ---------------- combined split-K reduction ----------------
// a0 final lands in kh=0 (L0 team), a1 final lands in kh=1 (L1 team).
// Uses hsA/hsB (dead after gemms) as scratch; leading bar orders gemm reads.
__device__ __forceinline__ void reduce_both(float* bufA, float* bufB,
                                            ull a0[8], ull a1[8], int kh, int w) {
    ull* rA = (ull*)bufA;
    ull* rB = (ull*)bufB;
    __syncthreads();
    if (kh) {
#pragma unroll
        for (int i = 0; i < 8; i++) rA[i * 128 + w] = a0[i];
    } else {
#pragma unroll
        for (int i = 0; i < 8; i++) rB[i * 128 + w] = a1[i];
    }
    __syncthreads();
    if (!kh) {
#pragma unroll
        for (int i = 0; i < 8; i++) add2(a0[i], rA[i * 128 + w]);
    } else {
#pragma unroll
        for (int i = 0; i < 8; i++) add2(a1[i], rB[i * 128 + w]);
    }
}

__device__ __forceinline__ float lstm_h(ull g01, ull g23, float& cs) {
    float iv, fv, gv, ov;
    unpk(g01, iv, fv); unpk(g23, gv, ov);
    cs = sigf(fv) * cs + sigf(iv) * tanha(gv);
    return sigf(ov) * tanha(cs);
}

// x-part of L0 gates for timestep t (4 batch rows rb..rb+3, unit txc)
__device__ __forceinline__ void xpart(const float* __restrict__ Wi0,
                                      int t, int rb, int txc, ull a[8]) {
    const float4* ep = (const float4*)(g_emb + (t * 256 + rb) * 8);
    float xv[4][8];
#pragma unroll
    for (int r = 0; r < 4; r++) {
        float4 u0 = ep[2 * r], u1 = ep[2 * r + 1];
        xv[r][0] = u0.x; xv[r][1] = u0.y; xv[r][2] = u0.z; xv[r][3] = u0.w;
        xv[r][4] = u1.x; xv[r][5] = u1.y; xv[r][6] = u1.z; xv[r][7] = u1.w;
    }
#pragma unroll
    for (int e = 0; e < 8; e++) {
        float4 wv = *(const float4*)(&Wi0[e * 32 + 4 * txc]);
        ull w01 = pk(wv.x, wv.y), w23 = pk(wv.z, wv.w);
#pragma unroll
        for (int r = 0; r < 4; r++) {
            ull xd = pk(xv[r][e], xv[r][e]);
            fma2(a[2 * r], w01, xd);
            fma2(a[2 * r + 1], w23, xd);
        }
    }
}

// ---------------- prep: embedding gather + barrier reset ----------------
__global__ void prep_kernel(const int* __restrict__ tokens,
                            const float* __restrict__ emb) {
    int idx = blockIdx.x * 256 + threadIdx.x;  // 0..65535
    if (idx == 0) g_bar = 0;
    int b = idx >> 8, t = idx & 255;
    int tok = tokens[b * 256 + t];
    const float4* e = (const float4*)(emb + tok * 8);
    float4* d = (float4*)(g_emb + (t * 256 + b) * 8);
    d[0] = e[0];
    d[1] = e[1];
}

// ---------------- persistent LSTM kernel ----------------
extern __shared__ float smem_raw[];

__global__ void __launch_bounds__(TPB, 1)
lstm_kernel(const int* __restrict__ lengths,
            const float* __restrict__ w_ih0, const float* __restrict__ w_hh0,
            const float* __restrict__ b_ih0, const float* __restrict__ b_hh0,
            const float* __restrict__ w_ih1, const float* __restrict__ w_hh1,
            const float* __restrict__ b_ih1, const float* __restrict__ b_hh1,
            const float* __restrict__ ff_w, const float* __restrict__ ff_b,
            const float* __restrict__ bn_g, const float* __restrict__ bn_b,
            float* __restrict__ out) {
    SmemLayout* S = (SmemLayout*)smem_raw;
    const int tid = threadIdx.x;
    const int bid = blockIdx.x;
    const int bg = bid >> 5;     // batch group 0..3 (64 rows)
    const int ug = bid & 31;     // unit group 0..31 (8 units)
    const int kh = tid >> 7;     // k-half team: 0 -> k[0,128) + L0 cell; 1 -> k[128,256) + L1 cell
    const int w  = tid & 127;
    const int txc = w & 7;       // unit within group
    const int txb = w >> 3;      // 0..15 -> rows 4*txb..4*txb+3
    const int koff = kh * 128;
    const int rb = bg * 64 + 4 * txb;
    const int u = ug * 8 + txc;

    // --- load + permute weights into SMEM ---
    for (int idx = tid; idx < 32 * 256; idx += TPB) {
        int c = idx & 31, k = idx >> 5;
        int uu = c >> 2, g = c & 3;
        int row = g * 256 + ug * 8 + uu;
        S->Wh0[k * 32 + c] = w_hh0[row * 256 + k];
        S->Wi1[k * 32 + c] = w_ih1[row * 256 + k];
        S->Wh1[k * 32 + c] = w_hh1[row * 256 + k];
    }
    if (tid < 8 * 32) {
        int c = tid & 31, e = tid >> 5;
        int uu = c >> 2, g = c & 3;
        int row = g * 256 + ug * 8 + uu;
        S->Wi0[e * 32 + c] = w_ih0[row * 8 + e];
    }
    if (tid < 32) {
        int uu = tid >> 2, g = tid & 3;
        int row = g * 256 + ug * 8 + uu;
        S->b0[tid] = b_ih0[row] + b_hh0[row];
        S->b1[tid] = b_ih1[row] + b_hh1[row];
    }
    // h2(-1) = 0 lives in g_h2[1] (read at phase 0)
    if (!kh) {
        *(float4*)(&g_h2[1][u * 256 + rb]) = make_float4(0.f, 0.f, 0.f, 0.f);
    }

    int4 ln4 = *(const int4*)(lengths + rb);
    int ln[4] = {ln4.x, ln4.y, ln4.z, ln4.w};
    float c1s[4] = {0.f, 0.f, 0.f, 0.f};
    float c2s[4] = {0.f, 0.f, 0.f, 0.f};
    unsigned gen = 0;
    __syncthreads();   // smem biases ready for prologue

    ull bi01_0 = pk(S->b0[4 * txc + 0], S->b0[4 * txc + 1]);
    ull bi23_0 = pk(S->b0[4 * txc + 2], S->b0[4 * txc + 3]);
    ull bi01_1 = pk(S->b1[4 * txc + 0], S->b1[4 * txc + 1]);
    ull bi23_1 = pk(S->b1[4 * txc + 2], S->b1[4 * txc + 3]);
    const ull Z = 0ull;

    // ---------- prologue: h1(0) = cell(x(0), 0)  (no cross-block sum needed) ----------
    if (!kh) {
        ull a0[8];
        a0[0] = a0[2] = a0[4] = a0[6] = bi01_0;
        a0[1] = a0[3] = a0[5] = a0[7] = bi23_0;
        xpart(S->Wi0, 0, rb, txc, a0);
        float h1v[4];
#pragma unroll
        for (int r = 0; r < 4; r++)
            h1v[r] = lstm_h(a0[2 * r], a0[2 * r + 1], c1s[r]);
        *(float4*)(&g_h1[0][u * 256 + rb]) =
            make_float4(h1v[0], h1v[1], h1v[2], h1v[3]);
    }
    grid_sync(gen);

    // ---------- main loop: phase p computes h1(p+1) and h2(p) ----------
    for (int p = 0; p < 255; p++) {
        const int cb = p & 1;   // h1(p) in g_h1[cb], h2(p-1) in g_h2[cb^1]

        stage_cg(S->hsA, g_h1[cb], bg, tid);      // h1(p)    group 0
        cpa_commit();
        stage_cg(S->hsB, g_h2[cb ^ 1], bg, tid);  // h2(p-1)  group 1
        cpa_commit();

        ull a0[8], a1[8];
        if (!kh) {
            a0[0] = a0[2] = a0[4] = a0[6] = bi01_0;
            a0[1] = a0[3] = a0[5] = a0[7] = bi23_0;
            xpart(S->Wi0, p + 1, rb, txc, a0);    // x(p+1), overlaps stage latency
#pragma unroll
            for (int i = 0; i < 8; i++) a1[i] = Z;
        } else {
#pragma unroll
            for (int i = 0; i < 8; i++) a0[i] = Z;
            a1[0] = a1[2] = a1[4] = a1[6] = bi01_1;
            a1[1] = a1[3] = a1[5] = a1[7] = bi23_1;
        }

        CPA_WAIT(1);
        __syncthreads();                          // hsA (h1(p)) ready
        gemm8h(S->Wh0, S->hsA, txc, txb, koff, a0);
        gemm8h(S->Wi1, S->hsA, txc, txb, koff, a1);

        CPA_WAIT(0);
        __syncthreads();                          // hsB (h2(p-1)) ready
        gemm8h(S->Wh1, S->hsB, txc, txb, koff, a1);

        reduce_both(S->hsA, S->hsB, a0, a1, kh, w);

        if (!kh) {
            float h1v[4];
#pragma unroll
            for (int r = 0; r < 4; r++)
                h1v[r] = lstm_h(a0[2 * r], a0[2 * r + 1], c1s[r]);
            *(float4*)(&g_h1[cb ^ 1][u * 256 + rb]) =
                make_float4(h1v[0], h1v[1], h1v[2], h1v[3]);   // h1(p+1)
        } else {
            float h2v[4];
#pragma unroll
            for (int r = 0; r < 4; r++)
                h2v[r] = lstm_h(a1[2 * r], a1[2 * r + 1], c2s[r]);
            *(float4*)(&g_h2[cb][u * 256 + rb]) =
                make_float4(h2v[0], h2v[1], h2v[2], h2v[3]);   // h2(p)
#pragma unroll
            for (int r = 0; r < 4; r++)
                if (p == ln[r] - 1) g_last[(rb + r) * 256 + u] = h2v[r];
        }

        grid_sync(gen);
    }

    // ---------- epilogue: h2(255) from h1(255) (buf 1) and h2(254) (buf 0) ----------
    {
        stage_cg(S->hsA, g_h1[1], bg, tid);
        cpa_commit();
        stage_cg(S->hsB, g_h2[0], bg, tid);
        cpa_commit();

        ull a1[8];
        if (kh) {
            a1[0] = a1[2] = a1[4] = a1[6] = bi01_1;
            a1[1] = a1[3] = a1[5] = a1[7] = bi23_1;
        } else {
#pragma unroll
            for (int i = 0; i < 8; i++) a1[i] = Z;
        }

        CPA_WAIT(1);
        __syncthreads();
        gemm8h(S->Wi1, S->hsA, txc, txb, koff, a1);
        CPA_WAIT(0);
        __syncthreads();
        gemm8h(S->Wh1, S->hsB, txc, txb, koff, a1);

        ull* rB = (ull*)S->hsB;
        __syncthreads();
        if (!kh) {
#pragma unroll
            for (int i = 0; i < 8; i++) rB[i * 128 + w] = a1[i];
        }
        __syncthreads();
        if (kh) {
#pragma unroll
            for (int i = 0; i < 8; i++) add2(a1[i], rB[i * 128 + w]);
            float h2v[4];
#pragma unroll
            for (int r = 0; r < 4; r++)
                h2v[r] = lstm_h(a1[2 * r], a1[2 * r + 1], c2s[r]);
#pragma unroll
            for (int r = 0; r < 4; r++)
                if (ln[r] == 256) g_last[(rb + r) * 256 + u] = h2v[r];
        }
    }

    grid_sync(gen);

    // ================= y = relu(last) @ ff_w^T + ff_b =================
    // block handles batch rows 2*bid, 2*bid+1; thread = col tid (256 cols)
    {
        float* sv = S->hsA;
        int br0 = 2 * bid, br1 = 2 * bid + 1;
        sv[tid]       = fmaxf(g_last[br0 * 256 + tid], 0.f);
        sv[256 + tid] = fmaxf(g_last[br1 * 256 + tid], 0.f);
        __syncthreads();
        float a0 = ff_b[tid], a1 = a0;
        const float4* wr = (const float4*)(ff_w + tid * 256);
        const float4* h0 = (const float4*)sv;
        const float4* h1 = (const float4*)(sv + 256);
#pragma unroll 4
        for (int k4 = 0; k4 < 64; k4++) {
            float4 wv = wr[k4];
            float4 ha = h0[k4], hb = h1[k4];
            a0 += wv.x * ha.x + wv.y * ha.y + wv.z * ha.z + wv.w * ha.w;
            a1 += wv.x * hb.x + wv.y * hb.y + wv.z * hb.z + wv.w * hb.w;
        }
        g_y[br0 * 256 + tid] = a0;
        g_y[br1 * 256 + tid] = a1;
    }

    grid_sync(gen);

    // ================= BatchNorm over batch axis =================
    // block handles cols 2*bid, 2*bid+1; thread = batch row tid (256 rows)
    {
        float* red = S->hsA;
        for (int r = 0; r < 2; r++) {
            int j = 2 * bid + r;
            float v = g_y[tid * 256 + j];
            __syncthreads();
            red[tid] = v;
            __syncthreads();
            for (int s = 128; s > 0; s >>= 1) {
                if (tid < s) red[tid] += red[tid + s];
                __syncthreads();
            }
            float mean = red[0] * (1.f / 256.f);
            __syncthreads();
            float d = v - mean;
            red[tid] = d * d;
            __syncthreads();
            for (int s = 128; s > 0; s >>= 1) {
                if (tid < s) red[tid] += red[tid + s];
                __syncthreads();
            }
            float inv = rsqrtf(red[0] * (1.f / 256.f) + 1e-5f);
            __syncthreads();
            out[tid * 256 + j] = bn_g[j] * d * inv + bn_b[j];
        }
    }
}

// ---------------- launch ----------------
extern "C" void kernel_launch(void* const* d_in, const int* in_sizes, int n_in,
                              void* d_out, int out_size) {
    const int*   tokens    = (const int*)d_in[0];
    const int*   lengths   = (const int*)d_in[1];
    const float* embedding = (const float*)d_in[2];
    const float* w_ih0     = (const float*)d_in[3];
    const float* w_hh0     = (const float*)d_in[4];
    const float* b_ih0     = (const float*)d_in[5];
    const float* b_hh0     = (const float*)d_in[6];
    const float* w_ih1     = (const float*)d_in[7];
    const float* w_hh1     = (const float*)d_in[8];
    const float* b_ih1     = (const float*)d_in[9];
    const float* b_hh1     = (const float*)d_in[10];
    const float* ff_w      = (const float*)d_in[11];
    const float* ff_b      = (const float*)d_in[12];
    const float* bn_g      = (const float*)d_in[13];
    const float* bn_b      = (const float*)d_in[14];
    float* out = (float*)d_out;

    cudaFuncSetAttribute(lstm_kernel, cudaFuncAttributeMaxDynamicSharedMemorySize,
                         (int)sizeof(SmemLayout));

    prep_kernel<<<256, 256>>>(tokens, embedding);
    lstm_kernel<<<NBLK, TPB, sizeof(SmemLayout)>>>(
        lengths, w_ih0, w_hh0, b_ih0, b_hh0,
        w_ih1, w_hh1, b_ih1, b_hh1,
        ff_w, ff_b, bn_g, bn_b, out);
}